// round 17
// baseline (speedup 1.0000x reference)
#include <cuda_runtime.h>
#include <cstdint>

#define B_      1024
#define T_      8192
#define NW_     2048
#define NTH     512
#define NWHOLE  888                       // rows 0..887: one whole-row block each
#define NHROWS  136                       // rows 888..1023: two half-row blocks each
#define NBLK    (NWHOLE + 2 * NHROWS)     // 1160 blocks; halves have the highest bids

__device__ float4       g_part[NBLK];     // accR, accP, accW, ds2(whole rows only)
__device__ float2       g_rs[2 * NHROWS]; // sp,sg per half block
__device__ float2       g_bwa[NHROWS];    // A-side straddle-word partial (x<0 => none)
__device__ float2       g_bwb[NHROWS];    // B-side straddle-word partial
__device__ unsigned int g_count = 0;

__device__ __forceinline__ float wsumf(float v) {
#pragma unroll
    for (int o = 16; o > 0; o >>= 1) v += __shfl_down_sync(0xffffffffu, v, o);
    return v;
}
__device__ __forceinline__ double wsumd(double v) {
#pragma unroll
    for (int o = 16; o > 0; o >>= 1) v += __shfl_down_sync(0xffffffffu, v, o);
    return v;
}

// The proven R12/R15/R16 stage body, parameterized by stage count + base offset.
template<int NS>
__device__ __forceinline__ void run_stages(
    const float* __restrict__ dpr, const float* __restrict__ gtr,
    const int*   __restrict__ wr,  const int*   __restrict__ tkr,
    const int jbase, const int tid, const int lane,
    const float* s_tab, float2* s_w, float4* s_h,
    uint64_t& accRP, float& sp, float& sg, int& defm)
{
    const uint64_t NEG1x2 = 0xBF800000BF800000ull;   // (-1.0f, -1.0f)
#pragma unroll
    for (int s = 0; s < NS; ++s) {
        const int j0 = jbase + s * (NTH * 4) + tid * 4;

        const float4 dp4 = *reinterpret_cast<const float4*>(dpr + j0);
        const float4 gt4 = *reinterpret_cast<const float4*>(gtr + j0);
        const int4   tk4 = *reinterpret_cast<const int4*>(tkr + j0);
        const int4   w4  = *reinterpret_cast<const int4*>(wr  + j0);

        // neighbor values: shuffle for lanes 0..30, global for warp-edge lanes
        float dpn0  = __shfl_down_sync(0xffffffffu, dp4.x, 1);
        int   wn    = __shfl_down_sync(0xffffffffu, w4.x,  1);
        int   wprev = __shfl_up_sync(0xffffffffu, w4.w, 1);
        float dpn1l = 1e30f; int tknl = 150;
        if (lane == 31) {
            if (j0 + 4 < T_) {
                dpn0  = dpr[j0 + 4]; dpn1l = dpr[j0 + 5];
                tknl  = tkr[j0 + 4]; wn    = wr[j0 + 4];
            } else {
                dpn0 = 1e30f; wn = -1;
            }
        }
        if (lane == 0) wprev = (j0 > 0) ? wr[j0 - 1] : -1;

        float dpv[5] = { dp4.x, dp4.y, dp4.z, dp4.w, dpn0 };
        float gtv[4] = { gt4.x, gt4.y, gt4.z, gt4.w };
        int   tkv[4] = { tk4.x, tk4.y, tk4.z, tk4.w };

        float g[5], sa[4];
#pragma unroll
        for (int k = 0; k < 4; ++k) {
            const float t  = s_tab[tkv[k]];
            const float g1 = fmaxf(dpv[k] - fabsf(t), 0.0f);
            const float g2 = (t < 0.0f)
                           ? fmaxf(dpv[k] - dpv[k + 1] * (1.0f / 3.0f), 0.0f)
                           : 0.0f;
            g[k]  = g1 + g2;
            sa[k] = (g2 > 0.0f) ? g2 : g1;
        }
        g[4] = __shfl_down_sync(0xffffffffu, g[0], 1);
        if (lane == 31) {
            const float tn = s_tab[tknl];
            const float a  = fmaxf(dpn0 - fabsf(tn), 0.0f);
            const float c  = (tn < 0.0f)
                           ? fmaxf(dpn0 - dpn1l * (1.0f / 3.0f), 0.0f)
                           : 0.0f;
            g[4] = a + c;
        }

#pragma unroll
        for (int k = 0; k < 4; ++k) {
            const float rules = dpv[k] - sa[k] + g[k + 1];
            const float la = __log2f(dpv[k] + 1.0f);
            const float lr = __log2f(rules  + 1.0f);
            const float lg = __log2f(gtv[k] + 1.0f);
            uint64_t lrg, la2, d2;
            asm("mov.b64 %0, {%1, %2};" : "=l"(lrg)
                : "r"(__float_as_uint(lr)), "r"(__float_as_uint(lg)));
            asm("mov.b64 %0, {%1, %1};" : "=l"(la2)
                : "r"(__float_as_uint(la)));
            asm("fma.rn.f32x2 %0, %1, %2, %3;" : "=l"(d2)
                : "l"(la2), "l"(NEG1x2), "l"(lrg));
            asm("fma.rn.f32x2 %0, %1, %1, %0;" : "+l"(accRP) : "l"(d2));
        }

        // branch-free word-segment bookkeeping (dur_pred >= 0: clamp is identity)
        const float Sp3 = dp4.w,       Sg3 = gt4.w;
        const float Sp2 = dp4.z + Sp3, Sg2 = gt4.z + Sg3;
        const float Sp1 = dp4.y + Sp2, Sg1 = gt4.y + Sg2;
        const float Sp0 = dp4.x + Sp1, Sg0 = gt4.x + Sg1;
        sp += Sp0;
        sg += Sg0;

        const bool bb0 = (w4.x != wprev);
        const bool bb1 = (w4.y != w4.x);
        const bool bb2 = (w4.z != w4.y);
        const bool bb3 = (w4.w != w4.z);
        const bool bb4 = (wn   != w4.w);

        const float SpN2 = bb3 ? Sp3 : 0.0f,  SgN2 = bb3 ? Sg3 : 0.0f;
        const float SpN1 = bb2 ? Sp2 : SpN2,  SgN1 = bb2 ? Sg2 : SgN2;
        const float SpN0 = bb1 ? Sp1 : SpN1,  SgN0 = bb1 ? Sg1 : SgN1;

        const bool t0 = !(bb1 || bb2 || bb3);

        const int c = s * NTH + tid;
        s_h[c] = make_float4(Sp0 - SpN0, Sg0 - SgN0,
                             __int_as_float(w4.x | (t0 ? (int)0x80000000 : 0)), 0.0f);

        if (bb0) s_w[w4.x] = make_float2(Sp0 - SpN0, Sg0 - SgN0);
        if (bb1) s_w[w4.y] = make_float2(Sp1 - SpN1, Sg1 - SgN1);
        if (bb2) s_w[w4.z] = make_float2(Sp2 - SpN2, Sg2 - SgN2);
        if (bb3) s_w[w4.w] = make_float2(Sp3,        Sg3);

        defm |= (int)(!bb4 && (bb0 || bb1 || bb2 || bb3)) << s;
    }
}

__global__ void __launch_bounds__(NTH, 2) duration_loss_fused(
    const float* __restrict__ dur_pred,
    const float* __restrict__ dur_gt,
    const int*   __restrict__ ph2word,
    const int*   __restrict__ txt_tokens,
    float* __restrict__ out)
{
    __shared__ float  s_tab[151];
    __shared__ float2 s_w[NW_];
    __shared__ float4 s_h[NW_];
    __shared__ float  s_red[5][NTH / 32];
    __shared__ double s_dred[4][NTH / 32];
    __shared__ int    s_islast, s_lo, s_hi, s_skip, s_bcont;

    const int tid  = threadIdx.x;
    const int lane = tid & 31;
    const int wid  = tid >> 5;
    const int bid  = blockIdx.x;

    const bool ishalf = (bid >= NWHOLE);
    const int  hix    = ishalf ? (bid - NWHOLE) : 0;   // 0..271
    const int  rowi   = hix >> 1;                      // 0..135
    const int  half   = hix & 1;
    const int  row    = ishalf ? (NWHOLE + rowi) : bid;
    const int  jbase  = ishalf ? half * (T_ / 2) : 0;
    const int  nelem  = ishalf ? (T_ / 2) : T_;
    const int  cmax   = nelem >> 2;                    // chunks in this region

    for (int i = tid; i < 151; i += NTH) {
        float ex = 1e30f;
        if (i == 94 || i == 100 || i == 92) ex = 2.0f;
        else if (i == 122)                  ex = 3.0f;
        else if (i == 43 || i == 27)        ex = 5.0f;
        const bool rt = (i == 44 || i == 28 || i == 29 || i == 27 || i == 121 || i == 43);
        s_tab[i] = rt ? -ex : ex;
    }
    for (int i = tid; i < NW_; i += NTH) s_w[i] = make_float2(0.0f, 0.0f);

    const float* dpr = dur_pred   + (size_t)row * T_;
    const float* gtr = dur_gt     + (size_t)row * T_;
    const int*   wr  = ph2word    + (size_t)row * T_;
    const int*   tkr = txt_tokens + (size_t)row * T_;

    if (tid == 0) {
        s_lo = wr[jbase];
        s_hi = wr[jbase + nelem - 1];
        int sk = 0, bc = 0;
        if (ishalf && half == 0 && wr[jbase + nelem - 1] == wr[jbase + nelem])
            sk = wr[jbase + nelem - 1];                 // word straddles the split
        if (ishalf && half == 1 && wr[jbase - 1] == wr[jbase])
            bc = 1;                                     // leading run continues from A
        s_skip = sk; s_bcont = bc;
    }
    __syncthreads();

    uint64_t accRP = 0ull;
    float sp = 0.0f, sg = 0.0f;
    int   defm = 0;

    if (!ishalf) run_stages<4>(dpr, gtr, wr, tkr, 0,     tid, lane, s_tab, s_w, s_h, accRP, sp, sg, defm);
    else         run_stages<2>(dpr, gtr, wr, tkr, jbase, tid, lane, s_tab, s_w, s_h, accRP, sp, sg, defm);
    __syncthreads();

    // resolve words spanning chunk boundaries (owner walks head-run chain)
#pragma unroll
    for (int s = 0; s < 4; ++s) {
        if ((defm >> s) & 1) {
            int ci = s * NTH + tid + 1;
            if (ci < cmax) {            // deferred at region end: partial already in s_w
                float4 h = s_h[ci];
                int m = __float_as_int(h.z);
                const int w = m & 0x7fffffff;
                const float2 pq = s_w[w];
                float p = pq.x, q = pq.y;
                while (true) {
                    p += h.x; q += h.y;
                    if (m >= 0) break;
                    if (++ci >= cmax) break;
                    h = s_h[ci];
                    m = __float_as_int(h.z);
                    if ((m & 0x7fffffff) != w) break;
                }
                s_w[w] = make_float2(p, q);
            }
        }
    }
    // B side: leading run continuing from A -> export partial (never enters s_w)
    if (ishalf && half == 1 && tid == 0 && s_bcont) {
        const int w = s_lo;
        float p = 0.0f, q = 0.0f;
        int ci = 0;
        while (ci < cmax) {
            const float4 h = s_h[ci];
            const int m = __float_as_int(h.z);
            if ((m & 0x7fffffff) != w) break;
            p += h.x; q += h.y;
            if (m >= 0) break;
            ++ci;
        }
        g_bwb[rowi] = make_float2(p, q);
    }
    __syncthreads();

    // A side: export straddle-word partial (accumulated in s_w by the defer walk)
    if (ishalf && half == 0 && tid == 0) {
        const int sk = s_skip;
        g_bwa[rowi] = (sk > 0) ? s_w[sk] : make_float2(-1.0f, 0.0f);
    }

    // word-level loss over this region's word range; skip straddle word on A side
    float accW = 0.0f;
    {
        const int lo = s_lo, hi = s_hi, sk = s_skip;
        for (int w = lo + tid; w <= hi; w += NTH) {
            if (w > 0 && w != sk) {
                const float2 wv2 = s_w[w];
                const float d = __log2f(wv2.x + 1.0f) - __log2f(wv2.y + 1.0f);
                accW = fmaf(d, d, accW);
            }
        }
    }

    float accR, accP;
    {
        unsigned lo32, hi32;
        asm("mov.b64 {%0, %1}, %2;" : "=r"(lo32), "=r"(hi32) : "l"(accRP));
        accR = __uint_as_float(lo32);
        accP = __uint_as_float(hi32);
    }

    // block reduction -> per-block partial
    float v[5] = { accR, accP, accW, sp, sg };
#pragma unroll
    for (int q = 0; q < 5; ++q) {
        const float r = wsumf(v[q]);
        if (lane == 0) s_red[q][wid] = r;
    }
    __syncthreads();
    if (wid == 0) {
        float t[5];
#pragma unroll
        for (int q = 0; q < 5; ++q) {
            float x = (lane < NTH / 32) ? s_red[q][lane] : 0.0f;
            t[q] = wsumf(x);
        }
        if (lane == 0) {
            if (!ishalf) {
                const float ds = __log2f(t[3] + 1.0f) - __log2f(t[4] + 1.0f);
                g_part[bid] = make_float4(t[0], t[1], t[2], ds * ds);
            } else {
                g_part[bid] = make_float4(t[0], t[1], t[2], 0.0f);
                g_rs[hix]   = make_float2(t[3], t[4]);
            }
            __threadfence();
            const unsigned tk = atomicAdd(&g_count, 1u);
            s_islast = (tk == (unsigned)(NBLK - 1));
        }
    }
    __syncthreads();

    if (s_islast) {
        __threadfence();
        double a0 = 0.0, a1 = 0.0, a2 = 0.0, a3 = 0.0;
        for (int i = tid; i < NBLK; i += NTH) {
            const float4 p = g_part[i];
            a0 += p.x; a1 += p.y; a2 += p.z; a3 += p.w;
        }
        for (int i = tid; i < NHROWS; i += NTH) {
            const float2 hA = g_rs[2 * i];
            const float2 hB = g_rs[2 * i + 1];
            const float ds = __log2f(hA.x + hB.x + 1.0f) - __log2f(hA.y + hB.y + 1.0f);
            a3 += (double)(ds * ds);
            const float2 wa = g_bwa[i];
            if (wa.x >= 0.0f) {
                const float2 wb = g_bwb[i];
                const float d = __log2f(wa.x + wb.x + 1.0f) - __log2f(wa.y + wb.y + 1.0f);
                a2 += (double)(d * d);
            }
        }
        double dv[4] = { a0, a1, a2, a3 };
#pragma unroll
        for (int q = 0; q < 4; ++q) {
            const double r = wsumd(dv[q]);
            if (lane == 0) s_dred[q][wid] = r;
        }
        __syncthreads();
        if (wid == 0) {
            double t[4];
#pragma unroll
            for (int q = 0; q < 4; ++q) {
                double x = (lane < NTH / 32) ? s_dred[q][lane] : 0.0;
                t[q] = wsumd(x);
            }
            if (lane == 0) {
                const double LN2SQ = 0.4804530139182014;   // ln(2)^2
                const double loss = LN2SQ * ((0.3 * t[0] + 0.6 * t[1]) / 8388608.0
                                           + 0.3 * t[2] / 2096128.0
                                           + 0.1 * t[3] / 1024.0);
                out[0] = (float)loss;
                g_count = 0;   // reset for next graph replay
            }
        }
    }
}

extern "C" void kernel_launch(void* const* d_in, const int* in_sizes, int n_in,
                              void* d_out, int out_size) {
    const float* dur_pred   = (const float*)d_in[0];
    const float* dur_gt     = (const float*)d_in[1];
    const int*   ph2word    = (const int*)d_in[2];
    const int*   txt_tokens = (const int*)d_in[3];
    duration_loss_fused<<<NBLK, NTH>>>(dur_pred, dur_gt, ph2word, txt_tokens, (float*)d_out);
}